// round 1
// baseline (speedup 1.0000x reference)
#include <cuda_runtime.h>
#include <cstdint>

// ExtractorMLP: per-edge MLP 128->256->64->1 with per-graph instance norm.
// Strategy: counting-sort edges by graph id so segment reductions are
// contiguous; fp32 SIMT GEMMs using packed fma.rn.f32x2 (FFMA2).

#define E_EDGES 1000000
#define EP      1000064   // padded to multiple of 128
#define NG      512
#define C1      256
#define C2      64
#define EPS_IN  1e-5f

typedef unsigned long long ull;

// ---------------- scratch (static __device__, allowed) ----------------
__device__ float g_x1[(size_t)EP * C1];   // layer-1 preacts, sorted order (1.02 GB)
__device__ float g_x2[(size_t)EP * C2];   // layer-2 preacts, sorted order (256 MB)
__device__ int   g_perm[EP];              // sorted pos -> original edge id
__device__ int   g_gid[EP];               // sorted pos -> graph id
__device__ int   g_cnt[NG];
__device__ int   g_off[NG + 1];
__device__ int   g_cur[NG];
__device__ float g_mean1[NG * C1];
__device__ float g_inv1 [NG * C1];
__device__ float g_mean2[NG * C2];
__device__ float g_inv2 [NG * C2];

// ---------------- packed f32x2 helpers ----------------
__device__ __forceinline__ ull pack2(float x, float y) {
    ull r; asm("mov.b64 %0, {%1, %2};" : "=l"(r) : "f"(x), "f"(y)); return r;
}
__device__ __forceinline__ void unpack2(ull v, float& x, float& y) {
    asm("mov.b64 {%0, %1}, %2;" : "=f"(x), "=f"(y) : "l"(v));
}
__device__ __forceinline__ void fma2(ull& d, ull a, ull b) {
    asm("fma.rn.f32x2 %0, %1, %2, %0;" : "+l"(d) : "l"(a), "l"(b));
}

// ---------------- sort pipeline ----------------
__global__ void k_zero() {
    int t = threadIdx.x;
    if (t < NG) g_cnt[t] = 0;
    if (t < (EP - E_EDGES)) { g_gid[E_EDGES + t] = 0; g_perm[E_EDGES + t] = 0; }
}

__global__ void k_hist(const int* __restrict__ col, const int* __restrict__ batch) {
    __shared__ int h[NG];
    int t = threadIdx.x;
    for (int g = t; g < NG; g += blockDim.x) h[g] = 0;
    __syncthreads();
    int idx = blockIdx.x * blockDim.x + t;
    int stride = gridDim.x * blockDim.x;
    for (int e = idx; e < E_EDGES; e += stride)
        atomicAdd(&h[batch[col[e]]], 1);
    __syncthreads();
    for (int g = t; g < NG; g += blockDim.x)
        if (h[g]) atomicAdd(&g_cnt[g], h[g]);
}

__global__ void k_scan() {
    __shared__ int s[NG];
    int t = threadIdx.x;
    int c = g_cnt[t];
    s[t] = c;
    __syncthreads();
    for (int o = 1; o < NG; o <<= 1) {
        int v = (t >= o) ? s[t - o] : 0;
        __syncthreads();
        s[t] += v;
        __syncthreads();
    }
    int excl = s[t] - c;
    g_off[t] = excl;
    g_cur[t] = excl;
    if (t == NG - 1) g_off[NG] = s[t];
}

__global__ void k_scatter(const int* __restrict__ col, const int* __restrict__ batch) {
    int idx = blockIdx.x * blockDim.x + threadIdx.x;
    int stride = gridDim.x * blockDim.x;
    for (int e = idx; e < E_EDGES; e += stride) {
        int g = batch[col[e]];
        int p = atomicAdd(&g_cur[g], 1);
        g_perm[p] = e;
        g_gid[p] = g;
    }
}

// ---------------- GEMM1: [64 edges x 256 ch], K=128 (concat col/row halves) ----------------
__global__ __launch_bounds__(256, 2) void k_gemm1(
    const float* __restrict__ emb, const float* __restrict__ W1,
    const int* __restrict__ col, const int* __restrict__ row)
{
    __shared__ float sA[64][68];    // [k within half][edge]
    __shared__ float sB[16][256];   // [k within chunk][channel]
    __shared__ int s_nd[64];
    int tid = threadIdx.x;
    int base = blockIdx.x * 64;     // E % 64 == 0, always full tile
    int er = tid >> 5, cr = tid & 31;

    ull acc[4][8];
    #pragma unroll
    for (int i = 0; i < 4; i++)
        #pragma unroll
        for (int j = 0; j < 8; j++) acc[i][j] = 0ull;

    for (int half = 0; half < 2; half++) {
        if (tid < 64) {
            int e = g_perm[base + tid];
            s_nd[tid] = half ? row[e] : col[e];
        }
        __syncthreads();
        {   // gather A tile transposed: sA[k][e] = emb[node_e][k]
            int ge = tid & 63, kb = tid >> 6;
            const float4* er4 = (const float4*)emb + (size_t)s_nd[ge] * 16;
            #pragma unroll
            for (int j = 0; j < 4; j++) {
                float4 v = er4[kb * 4 + j];
                int k = (kb * 4 + j) * 4;
                sA[k    ][ge] = v.x;
                sA[k + 1][ge] = v.y;
                sA[k + 2][ge] = v.z;
                sA[k + 3][ge] = v.w;
            }
        }
        __syncthreads();
        for (int kc = 0; kc < 4; kc++) {
            {   // load B chunk: W1 rows half*64 + kc*16 .. +16
                int c4 = tid & 63, kk0 = tid >> 6;
                #pragma unroll
                for (int j = 0; j < 4; j++) {
                    int kk = kk0 + 4 * j;
                    ((float4*)sB[kk])[c4] =
                        ((const float4*)W1)[(size_t)(half * 64 + kc * 16 + kk) * 64 + c4];
                }
            }
            __syncthreads();
            #pragma unroll
            for (int kk = 0; kk < 16; kk++) {
                ulonglong2 av0 = *(const ulonglong2*)&sA[kc * 16 + kk][er * 8];
                ulonglong2 av1 = *(const ulonglong2*)&sA[kc * 16 + kk][er * 8 + 4];
                ull pa[4] = {av0.x, av0.y, av1.x, av1.y};
                float4 b0 = *(const float4*)&sB[kk][cr * 8];
                float4 b1 = *(const float4*)&sB[kk][cr * 8 + 4];
                float bs[8] = {b0.x, b0.y, b0.z, b0.w, b1.x, b1.y, b1.z, b1.w};
                #pragma unroll
                for (int j = 0; j < 8; j++) {
                    ull bb = pack2(bs[j], bs[j]);
                    #pragma unroll
                    for (int i2 = 0; i2 < 4; i2++) fma2(acc[i2][j], pa[i2], bb);
                }
            }
            __syncthreads();
        }
    }
    // store x1 (no bias: b1 cancels under instance norm)
    #pragma unroll
    for (int i2 = 0; i2 < 4; i2++) {
        float lo[8], hi[8];
        #pragma unroll
        for (int j = 0; j < 8; j++) unpack2(acc[i2][j], lo[j], hi[j]);
        size_t p0 = (size_t)base + er * 8 + 2 * i2;
        float* r0 = g_x1 + p0 * C1 + cr * 8;
        float* r1 = r0 + C1;
        ((float4*)r0)[0] = make_float4(lo[0], lo[1], lo[2], lo[3]);
        ((float4*)r0)[1] = make_float4(lo[4], lo[5], lo[6], lo[7]);
        ((float4*)r1)[0] = make_float4(hi[0], hi[1], hi[2], hi[3]);
        ((float4*)r1)[1] = make_float4(hi[4], hi[5], hi[6], hi[7]);
    }
}

// ---------------- stats: per (graph, 32-channel chunk), contiguous reduction ----------------
__global__ void k_stats1() {
    int g  = blockIdx.x >> 3;
    int c0 = (blockIdx.x & 7) * 32;
    int t = threadIdx.x;
    int c = c0 + (t & 31), r = t >> 5;
    int s = g_off[g], eend = g_off[g + 1];
    float S = 0.f, Q = 0.f;
    for (int p = s + r; p < eend; p += 8) {
        float v = g_x1[(size_t)p * C1 + c];
        S += v; Q += v * v;
    }
    __shared__ float sS[256], sQ[256];
    sS[t] = S; sQ[t] = Q;
    __syncthreads();
    for (int h2 = 128; h2 >= 32; h2 >>= 1) {
        if (t < h2) { sS[t] += sS[t + h2]; sQ[t] += sQ[t + h2]; }
        __syncthreads();
    }
    if (t < 32) {
        float cnt = (float)max(eend - s, 1);
        float m = sS[t] / cnt;
        float var = sQ[t] / cnt - m * m;
        g_mean1[g * C1 + c0 + t] = m;
        g_inv1 [g * C1 + c0 + t] = rsqrtf(var + EPS_IN);
    }
}

__global__ void k_stats2() {
    int g  = blockIdx.x >> 1;
    int c0 = (blockIdx.x & 1) * 32;
    int t = threadIdx.x;
    int c = c0 + (t & 31), r = t >> 5;
    int s = g_off[g], eend = g_off[g + 1];
    float S = 0.f, Q = 0.f;
    for (int p = s + r; p < eend; p += 8) {
        float v = g_x2[(size_t)p * C2 + c];
        S += v; Q += v * v;
    }
    __shared__ float sS[256], sQ[256];
    sS[t] = S; sQ[t] = Q;
    __syncthreads();
    for (int h2 = 128; h2 >= 32; h2 >>= 1) {
        if (t < h2) { sS[t] += sS[t + h2]; sQ[t] += sQ[t + h2]; }
        __syncthreads();
    }
    if (t < 32) {
        float cnt = (float)max(eend - s, 1);
        float m = sS[t] / cnt;
        float var = sQ[t] / cnt - m * m;
        g_mean2[g * C2 + c0 + t] = m;
        g_inv2 [g * C2 + c0 + t] = rsqrtf(var + EPS_IN);
    }
}

// ---------------- GEMM2: [128 edges x 64 ch], K=256, norm+relu fused on load ----------------
__global__ __launch_bounds__(256) void k_gemm2(const float* __restrict__ W2)
{
    __shared__ float sX[16][132];
    __shared__ float sW[16][64];
    __shared__ int sgid[128];
    int tid = threadIdx.x;
    int base = blockIdx.x * 128;
    int er = tid >> 4, cr = tid & 15;
    if (tid < 128) sgid[tid] = g_gid[base + tid];

    ull acc[4][4];
    #pragma unroll
    for (int i = 0; i < 4; i++)
        #pragma unroll
        for (int j = 0; j < 4; j++) acc[i][j] = 0ull;

    for (int kc = 0; kc < 16; kc++) {
        __syncthreads();  // protects sX/sW reuse + sgid first use
        #pragma unroll
        for (int j = 0; j < 2; j++) {
            int f = tid + 256 * j;
            int e = f >> 2, q = f & 3;
            int pos = base + e;
            float4 v = make_float4(0.f, 0.f, 0.f, 0.f);
            if (pos < E_EDGES) {
                int g = sgid[e];
                float4 x  = ((const float4*)g_x1)[(size_t)pos * 64 + kc * 4 + q];
                float4 m  = ((const float4*)g_mean1)[g * 64 + kc * 4 + q];
                float4 iv = ((const float4*)g_inv1)[g * 64 + kc * 4 + q];
                v.x = fmaxf((x.x - m.x) * iv.x, 0.f);
                v.y = fmaxf((x.y - m.y) * iv.y, 0.f);
                v.z = fmaxf((x.z - m.z) * iv.z, 0.f);
                v.w = fmaxf((x.w - m.w) * iv.w, 0.f);
            }
            int k = q * 4;
            sX[k    ][e] = v.x;
            sX[k + 1][e] = v.y;
            sX[k + 2][e] = v.z;
            sX[k + 3][e] = v.w;
        }
        {
            int kk = tid >> 4, c4 = tid & 15;
            ((float4*)sW[kk])[c4] = ((const float4*)W2)[(size_t)(kc * 16 + kk) * 16 + c4];
        }
        __syncthreads();
        #pragma unroll
        for (int kk = 0; kk < 16; kk++) {
            ulonglong2 av0 = *(const ulonglong2*)&sX[kk][er * 8];
            ulonglong2 av1 = *(const ulonglong2*)&sX[kk][er * 8 + 4];
            ull pa[4] = {av0.x, av0.y, av1.x, av1.y};
            float4 bv = *(const float4*)&sW[kk][cr * 4];
            float bs[4] = {bv.x, bv.y, bv.z, bv.w};
            #pragma unroll
            for (int j = 0; j < 4; j++) {
                ull bb = pack2(bs[j], bs[j]);
                #pragma unroll
                for (int i2 = 0; i2 < 4; i2++) fma2(acc[i2][j], pa[i2], bb);
            }
        }
    }
    // store x2 (b2 cancels under norm)
    #pragma unroll
    for (int i2 = 0; i2 < 4; i2++) {
        float lo[4], hi[4];
        #pragma unroll
        for (int j = 0; j < 4; j++) unpack2(acc[i2][j], lo[j], hi[j]);
        int p0 = base + er * 8 + 2 * i2;   // p0 even, E even -> p0<E implies p0+1<E
        if (p0 < E_EDGES) {
            *((float4*)(g_x2 + (size_t)p0 * C2 + cr * 4)) =
                make_float4(lo[0], lo[1], lo[2], lo[3]);
            *((float4*)(g_x2 + (size_t)(p0 + 1) * C2 + cr * 4)) =
                make_float4(hi[0], hi[1], hi[2], hi[3]);
        }
    }
}

// ---------------- final: out[orig_e] = relu(norm(x2)) @ W3 + b3 ----------------
__global__ void k_final(const float* __restrict__ W3, const float* __restrict__ b3,
                        float* __restrict__ out)
{
    __shared__ float sw[64];
    int tid = threadIdx.x;
    if (tid < 64) sw[tid] = W3[tid];
    __syncthreads();
    int pos = blockIdx.x * 128 + (tid >> 1);
    int half = tid & 1;
    float acc = 0.f;
    if (pos < E_EDGES) {
        int g = g_gid[pos];
        const float4* xr = (const float4*)g_x2    + (size_t)pos * 16 + half * 8;
        const float4* mr = (const float4*)g_mean2 + g * 16 + half * 8;
        const float4* vr = (const float4*)g_inv2  + g * 16 + half * 8;
        #pragma unroll
        for (int j = 0; j < 8; j++) {
            float4 x = xr[j], m = mr[j], iv = vr[j];
            int k = half * 32 + j * 4;
            acc += fmaxf((x.x - m.x) * iv.x, 0.f) * sw[k]
                 + fmaxf((x.y - m.y) * iv.y, 0.f) * sw[k + 1]
                 + fmaxf((x.z - m.z) * iv.z, 0.f) * sw[k + 2]
                 + fmaxf((x.w - m.w) * iv.w, 0.f) * sw[k + 3];
        }
    }
    float other = __shfl_xor_sync(0xffffffffu, acc, 1);
    if (half == 0 && pos < E_EDGES) out[g_perm[pos]] = acc + other + b3[0];
}

// ---------------- launch ----------------
extern "C" void kernel_launch(void* const* d_in, const int* in_sizes, int n_in,
                              void* d_out, int out_size)
{
    const float* emb   = (const float*)d_in[0];
    const float* W1    = (const float*)d_in[1];
    const float* W2    = (const float*)d_in[3];
    const float* W3    = (const float*)d_in[5];
    const float* b3    = (const float*)d_in[6];
    const int*   ei    = (const int*)d_in[7];
    const int*   batch = (const int*)d_in[8];
    const int* col = ei;
    const int* row = ei + E_EDGES;
    float* out = (float*)d_out;

    k_zero<<<1, 512>>>();
    k_hist<<<1024, 256>>>(col, batch);
    k_scan<<<1, 512>>>();
    k_scatter<<<1024, 256>>>(col, batch);
    k_gemm1<<<E_EDGES / 64, 256>>>(emb, W1, col, row);
    k_stats1<<<NG * 8, 256>>>();
    k_gemm2<<<EP / 128, 256>>>(W2);
    k_stats2<<<NG * 2, 256>>>();
    k_final<<<EP / 128, 256>>>(W3, b3, out);
}

// round 4
// speedup vs baseline: 1.0897x; 1.0897x over previous
#include <cuda_runtime.h>
#include <cuda_bf16.h>
#include <cstdint>

// ExtractorMLP: per-edge MLP 128->256->64->1 with per-graph instance norm.
// R3: both GEMMs on mma.sync.m16n8k16 bf16 with 3-term hi/lo split
//     (base-PTX, no tcgen05 — harness compiles at plain sm_103 target).
//     Fragment-direct SMEM layouts, persistent GEMM kernels.

#define E_EDGES 1000000
#define EP      1000064   // multiple of 128
#define NG      512
#define C1      256
#define C2      64
#define EPS_IN  1e-5f
#define NTILES  (EP / 128)   // 7813
#define PGRID   148

typedef unsigned long long ull;
typedef unsigned int u32;

// ---------------- scratch ----------------
__device__ float g_x1[(size_t)EP * C1];
__device__ float g_x2[(size_t)EP * C2];
__device__ int   g_perm[EP];
__device__ int   g_gid[EP];
__device__ int   g_cnt[NG];
__device__ int   g_off[NG + 1];
__device__ int   g_cur[NG];
__device__ float g_mean1[NG * C1];
__device__ float g_inv1 [NG * C1];
__device__ float g_mean2[NG * C2];
__device__ float g_inv2 [NG * C2];
// W1 / W2 pre-split bf16 hi/lo in mma-fragment-direct order (dense, 64 u32/atom)
__device__ u32 g_B1hi[16384], g_B1lo[16384];   // 256 atoms (ni 32 x ki 8)
__device__ u32 g_B2hi[8192],  g_B2lo[8192];    // 128 atoms (ni 8  x ki 16)

// ---------------- helpers ----------------
__device__ __forceinline__ void bsplit(float x, float y, u32& h, u32& l) {
    __nv_bfloat162 hh = __floats2bfloat162_rn(x, y);
    float hx = __bfloat162float(hh.x);
    float hy = __bfloat162float(hh.y);
    __nv_bfloat162 ll = __floats2bfloat162_rn(x - hx, y - hy);
    h = *reinterpret_cast<u32*>(&hh);
    l = *reinterpret_cast<u32*>(&ll);
}

__device__ __forceinline__ void mma_bf16(float* d, const u32* a, const u32* b) {
    asm volatile(
        "mma.sync.aligned.m16n8k16.row.col.f32.bf16.bf16.f32 "
        "{%0,%1,%2,%3}, {%4,%5,%6,%7}, {%8,%9}, {%0,%1,%2,%3};"
        : "+f"(d[0]), "+f"(d[1]), "+f"(d[2]), "+f"(d[3])
        : "r"(a[0]), "r"(a[1]), "r"(a[2]), "r"(a[3]), "r"(b[0]), "r"(b[1]));
}

// A fragment scatter-store: element pair (bf16x2) at (m-local ml, k-pair kp)
// lands at lane=(ml&7)*4+(kp&3), reg=(ml>>3)+2*((kp&7)>>2), atom ki=kp>>3.
__device__ __forceinline__ void a_store(u32* hiB, u32* loB, int atom_base_x_stride,
                                        int ml, int kpl, u32 h, u32 l) {
    int off = atom_base_x_stride + ((ml & 7) * 4 + (kpl & 3)) * 4
            + (ml >> 3) + 2 * (kpl >> 2);
    hiB[off] = h; loB[off] = l;
}

// ---------------- sort pipeline ----------------
__global__ void k_zero() {
    int t = threadIdx.x;
    if (t < NG) g_cnt[t] = 0;
    if (t < (EP - E_EDGES)) { g_gid[E_EDGES + t] = 0; g_perm[E_EDGES + t] = 0; }
}

// W1 [128,256]: frag (n,k) value = W1[k*256+n]
__global__ void k_prep1(const float* __restrict__ W1) {
    int idx = blockIdx.x * blockDim.x + threadIdx.x;
    if (idx >= 16384) return;
    int a = idx >> 6, l = (idx >> 1) & 31, r = idx & 1;
    int ng = a >> 3, ki = a & 7;
    int k = ki * 16 + (l & 3) * 2 + r * 8;
    int n = ng * 8 + (l >> 2);
    float v0 = W1[k * 256 + n], v1 = W1[(k + 1) * 256 + n];
    u32 h, lo; bsplit(v0, v1, h, lo);
    g_B1hi[idx] = h; g_B1lo[idx] = lo;
}

// W2 [256,64]
__global__ void k_prep2(const float* __restrict__ W2) {
    int idx = blockIdx.x * blockDim.x + threadIdx.x;
    if (idx >= 8192) return;
    int a = idx >> 6, l = (idx >> 1) & 31, r = idx & 1;
    int ng = a >> 4, ki = a & 15;
    int k = ki * 16 + (l & 3) * 2 + r * 8;
    int n = ng * 8 + (l >> 2);
    float v0 = W2[k * 64 + n], v1 = W2[(k + 1) * 64 + n];
    u32 h, lo; bsplit(v0, v1, h, lo);
    g_B2hi[idx] = h; g_B2lo[idx] = lo;
}

__global__ void k_hist(const int* __restrict__ col, const int* __restrict__ batch) {
    __shared__ int h[NG];
    int t = threadIdx.x;
    for (int g = t; g < NG; g += blockDim.x) h[g] = 0;
    __syncthreads();
    int idx = blockIdx.x * blockDim.x + t;
    int stride = gridDim.x * blockDim.x;
    for (int e = idx; e < E_EDGES; e += stride)
        atomicAdd(&h[batch[col[e]]], 1);
    __syncthreads();
    for (int g = t; g < NG; g += blockDim.x)
        if (h[g]) atomicAdd(&g_cnt[g], h[g]);
}

__global__ void k_scan() {
    __shared__ int s[NG];
    int t = threadIdx.x;
    int c = g_cnt[t];
    s[t] = c;
    __syncthreads();
    for (int o = 1; o < NG; o <<= 1) {
        int v = (t >= o) ? s[t - o] : 0;
        __syncthreads();
        s[t] += v;
        __syncthreads();
    }
    int excl = s[t] - c;
    g_off[t] = excl;
    g_cur[t] = excl;
    if (t == NG - 1) g_off[NG] = s[t];
}

__global__ void k_scatter(const int* __restrict__ col, const int* __restrict__ batch) {
    __shared__ int sg[2048];
    __shared__ int hist[NG], base_[NG], cnt2[NG];
    int t = threadIdx.x;
    for (int g = t; g < NG; g += 256) { hist[g] = 0; cnt2[g] = 0; }
    __syncthreads();
    int e0 = blockIdx.x * 2048;
    #pragma unroll
    for (int j = 0; j < 8; j++) {
        int e = e0 + t + j * 256;
        int g = -1;
        if (e < E_EDGES) { g = batch[col[e]]; atomicAdd(&hist[g], 1); }
        sg[t + j * 256] = g;
    }
    __syncthreads();
    for (int g = t; g < NG; g += 256)
        if (hist[g]) base_[g] = atomicAdd(&g_cur[g], hist[g]);
    __syncthreads();
    #pragma unroll
    for (int j = 0; j < 8; j++) {
        int e = e0 + t + j * 256;
        if (e < E_EDGES) {
            int g = sg[t + j * 256];
            int l = atomicAdd(&cnt2[g], 1);
            int p = base_[g] + l;
            g_perm[p] = e;
            g_gid[p] = g;
        }
    }
}

// ---------------- GEMM1: mma.sync bf16 3-term; M=128,N=256,K=128 per tile ----------------
// smem (u32): [0) B1hi 256*66 | [16896) B1lo | [33792) A hi 64*132 | [42240) A lo | = 50688
__global__ __launch_bounds__(512, 1) void k_gemm1_mma(
    const float* __restrict__ emb,
    const int* __restrict__ col, const int* __restrict__ row)
{
    extern __shared__ u32 sm[];
    u32* sBhi = sm;
    u32* sBlo = sm + 16896;
    u32* sAhi = sm + 33792;
    u32* sAlo = sm + 42240;
    __shared__ int s_nd[2][128];

    int tid = threadIdx.x;
    // one-time: W1 frags -> smem (dense 64 -> padded 66 per atom)
    for (int i = tid; i < 16384; i += 512) {
        int a = i >> 6, j = i & 63;
        sBhi[a * 66 + j] = g_B1hi[i];
        sBlo[a * 66 + j] = g_B1lo[i];
    }

    int w = tid >> 5, lane = tid & 31;
    int wm = w & 3, wn = w >> 2;        // M 32-slice, N 64-slice
    int m = tid >> 2, q = tid & 3;      // gather role
    int mi = m >> 4, ml = m & 15;

    for (int tile = blockIdx.x; tile < NTILES; tile += PGRID) {
        int base = tile * 128;
        if (tid < 128) {
            int e = g_perm[base + tid];
            s_nd[0][tid] = col[e];
            s_nd[1][tid] = row[e];
        }
        __syncthreads();
        // gather + split: edge m, k range [q*32, q*32+32)
        {
            int node = s_nd[q >> 1][m];
            const float4* src = (const float4*)(emb + (size_t)node * 64 + (q & 1) * 32);
            #pragma unroll
            for (int jj = 0; jj < 8; jj++) {
                float4 v = src[jj];
                u32 h0, l0, h1, l1;
                bsplit(v.x, v.y, h0, l0);
                bsplit(v.z, v.w, h1, l1);
                int kp0 = q * 16 + jj * 2;
                int ab0 = (mi * 8 + (kp0 >> 3)) * 132;
                a_store(sAhi, sAlo, ab0, ml, kp0 & 7, h0, l0);
                int kp1 = kp0 + 1;
                int ab1 = (mi * 8 + (kp1 >> 3)) * 132;
                a_store(sAhi, sAlo, ab1, ml, kp1 & 7, h1, l1);
            }
        }
        __syncthreads();
        // mma
        float d[2][8][4];
        #pragma unroll
        for (int i2 = 0; i2 < 2; i2++)
            #pragma unroll
            for (int ni = 0; ni < 8; ni++)
                #pragma unroll
                for (int r = 0; r < 4; r++) d[i2][ni][r] = 0.f;

        #pragma unroll
        for (int ki = 0; ki < 8; ki++) {
            u32 ah[2][4], al[2][4];
            #pragma unroll
            for (int mi2 = 0; mi2 < 2; mi2++) {
                int atom = ((wm * 2 + mi2) * 8 + ki) * 132 + lane * 4;
                uint4 vh = *(const uint4*)(sAhi + atom);
                uint4 vl = *(const uint4*)(sAlo + atom);
                ah[mi2][0] = vh.x; ah[mi2][1] = vh.y; ah[mi2][2] = vh.z; ah[mi2][3] = vh.w;
                al[mi2][0] = vl.x; al[mi2][1] = vl.y; al[mi2][2] = vl.z; al[mi2][3] = vl.w;
            }
            #pragma unroll
            for (int ni = 0; ni < 8; ni++) {
                int batom = ((wn * 8 + ni) * 8 + ki) * 66 + lane * 2;
                uint2 bh = *(const uint2*)(sBhi + batom);
                uint2 bl = *(const uint2*)(sBlo + batom);
                u32 bhv[2] = {bh.x, bh.y};
                u32 blv[2] = {bl.x, bl.y};
                mma_bf16(d[0][ni], ah[0], bhv);
                mma_bf16(d[1][ni], ah[1], bhv);
                mma_bf16(d[0][ni], ah[0], blv);
                mma_bf16(d[1][ni], ah[1], blv);
                mma_bf16(d[0][ni], al[0], bhv);
                mma_bf16(d[1][ni], al[1], bhv);
            }
        }
        // epilogue -> g_x1 (no bias: b1 cancels under instance norm)
        {
            int r0base = base + wm * 32 + (lane >> 2);
            int cbase = wn * 64 + (lane & 3) * 2;
            #pragma unroll
            for (int mi2 = 0; mi2 < 2; mi2++) {
                size_t rA = (size_t)(r0base + mi2 * 16);
                size_t rB = rA + 8;
                #pragma unroll
                for (int ni = 0; ni < 8; ni++) {
                    int c = cbase + ni * 8;
                    *(float2*)(g_x1 + rA * C1 + c) = make_float2(d[mi2][ni][0], d[mi2][ni][1]);
                    *(float2*)(g_x1 + rB * C1 + c) = make_float2(d[mi2][ni][2], d[mi2][ni][3]);
                }
            }
        }
        __syncthreads();
    }
}

// ---------------- stats ----------------
__global__ void k_stats1() {
    int g  = blockIdx.x >> 3;
    int c0 = (blockIdx.x & 7) * 32;
    int t = threadIdx.x;
    int c = c0 + (t & 31), r = t >> 5;
    int s = g_off[g], eend = g_off[g + 1];
    float S = 0.f, Q = 0.f;
    for (int p = s + r; p < eend; p += 8) {
        float v = g_x1[(size_t)p * C1 + c];
        S += v; Q += v * v;
    }
    __shared__ float sS[256], sQ[256];
    sS[t] = S; sQ[t] = Q;
    __syncthreads();
    for (int h2 = 128; h2 >= 32; h2 >>= 1) {
        if (t < h2) { sS[t] += sS[t + h2]; sQ[t] += sQ[t + h2]; }
        __syncthreads();
    }
    if (t < 32) {
        float cnt = (float)max(eend - s, 1);
        float m = sS[t] / cnt;
        float var = sQ[t] / cnt - m * m;
        g_mean1[g * C1 + c0 + t] = m;
        g_inv1 [g * C1 + c0 + t] = rsqrtf(var + EPS_IN);
    }
}

__global__ void k_stats2() {
    int g  = blockIdx.x >> 1;
    int c0 = (blockIdx.x & 1) * 32;
    int t = threadIdx.x;
    int c = c0 + (t & 31), r = t >> 5;
    int s = g_off[g], eend = g_off[g + 1];
    float S = 0.f, Q = 0.f;
    for (int p = s + r; p < eend; p += 8) {
        float v = g_x2[(size_t)p * C2 + c];
        S += v; Q += v * v;
    }
    __shared__ float sS[256], sQ[256];
    sS[t] = S; sQ[t] = Q;
    __syncthreads();
    for (int h2 = 128; h2 >= 32; h2 >>= 1) {
        if (t < h2) { sS[t] += sS[t + h2]; sQ[t] += sQ[t + h2]; }
        __syncthreads();
    }
    if (t < 32) {
        float cnt = (float)max(eend - s, 1);
        float m = sS[t] / cnt;
        float var = sQ[t] / cnt - m * m;
        g_mean2[g * C2 + c0 + t] = m;
        g_inv2 [g * C2 + c0 + t] = rsqrtf(var + EPS_IN);
    }
}

// ---------------- GEMM2: mma.sync bf16 3-term; M=128,N=64,K=256 per tile ----------------
// smem (u32): [0) B2hi 128*66 | [8448) B2lo | [16896) A hi 128*132 | [33792) A lo | = 50688
__global__ __launch_bounds__(512, 1) void k_gemm2_mma()
{
    extern __shared__ u32 sm[];
    u32* sBhi = sm;
    u32* sBlo = sm + 8448;
    u32* sAhi = sm + 16896;
    u32* sAlo = sm + 33792;

    int tid = threadIdx.x;
    for (int i = tid; i < 8192; i += 512) {
        int a = i >> 6, j = i & 63;
        sBhi[a * 66 + j] = g_B2hi[i];
        sBlo[a * 66 + j] = g_B2lo[i];
    }

    int w = tid >> 5, lane = tid & 31;
    int wm = w & 3, wn = w >> 2;        // M 32-slice, N 16-slice
    int m = tid >> 2, q = tid & 3;
    int mi = m >> 4, ml = m & 15;

    for (int tile = blockIdx.x; tile < NTILES; tile += PGRID) {
        int base = tile * 128;
        __syncthreads();
        // gather: x1 row (sorted, contiguous) -> norm+relu -> split -> frag smem
        {
            int pos = base + m;
            int g = g_gid[pos];
            const float4* xr = (const float4*)(g_x1 + (size_t)pos * C1 + q * 64);
            const float4* mr = (const float4*)(g_mean1 + g * C1 + q * 64);
            const float4* vr = (const float4*)(g_inv1 + g * C1 + q * 64);
            #pragma unroll
            for (int jj = 0; jj < 16; jj++) {
                float4 x = xr[jj], mm = mr[jj], iv = vr[jj];
                float v0 = fmaxf((x.x - mm.x) * iv.x, 0.f);
                float v1 = fmaxf((x.y - mm.y) * iv.y, 0.f);
                float v2 = fmaxf((x.z - mm.z) * iv.z, 0.f);
                float v3 = fmaxf((x.w - mm.w) * iv.w, 0.f);
                u32 h0, l0, h1, l1;
                bsplit(v0, v1, h0, l0);
                bsplit(v2, v3, h1, l1);
                int kp0 = q * 32 + jj * 2;
                int ab0 = (mi * 16 + (kp0 >> 3)) * 132;
                a_store(sAhi, sAlo, ab0, ml, kp0 & 7, h0, l0);
                int kp1 = kp0 + 1;
                int ab1 = (mi * 16 + (kp1 >> 3)) * 132;
                a_store(sAhi, sAlo, ab1, ml, kp1 & 7, h1, l1);
            }
        }
        __syncthreads();
        float d[2][2][4];
        #pragma unroll
        for (int i2 = 0; i2 < 2; i2++)
            #pragma unroll
            for (int ni = 0; ni < 2; ni++)
                #pragma unroll
                for (int r = 0; r < 4; r++) d[i2][ni][r] = 0.f;

        #pragma unroll
        for (int ki = 0; ki < 16; ki++) {
            u32 ah[2][4], al[2][4];
            #pragma unroll
            for (int mi2 = 0; mi2 < 2; mi2++) {
                int atom = ((wm * 2 + mi2) * 16 + ki) * 132 + lane * 4;
                uint4 vh = *(const uint4*)(sAhi + atom);
                uint4 vl = *(const uint4*)(sAlo + atom);
                ah[mi2][0] = vh.x; ah[mi2][1] = vh.y; ah[mi2][2] = vh.z; ah[mi2][3] = vh.w;
                al[mi2][0] = vl.x; al[mi2][1] = vl.y; al[mi2][2] = vl.z; al[mi2][3] = vl.w;
            }
            #pragma unroll
            for (int ni = 0; ni < 2; ni++) {
                int batom = ((wn * 2 + ni) * 16 + ki) * 66 + lane * 2;
                uint2 bh = *(const uint2*)(sBhi + batom);
                uint2 bl = *(const uint2*)(sBlo + batom);
                u32 bhv[2] = {bh.x, bh.y};
                u32 blv[2] = {bl.x, bl.y};
                mma_bf16(d[0][ni], ah[0], bhv);
                mma_bf16(d[1][ni], ah[1], bhv);
                mma_bf16(d[0][ni], ah[0], blv);
                mma_bf16(d[1][ni], ah[1], blv);
                mma_bf16(d[0][ni], al[0], bhv);
                mma_bf16(d[1][ni], al[1], bhv);
            }
        }
        {
            int r0base = base + wm * 32 + (lane >> 2);
            int cbase = wn * 16 + (lane & 3) * 2;
            #pragma unroll
            for (int mi2 = 0; mi2 < 2; mi2++) {
                size_t rA = (size_t)(r0base + mi2 * 16);
                size_t rB = rA + 8;
                #pragma unroll
                for (int ni = 0; ni < 2; ni++) {
                    int c = cbase + ni * 8;
                    *(float2*)(g_x2 + rA * C2 + c) = make_float2(d[mi2][ni][0], d[mi2][ni][1]);
                    *(float2*)(g_x2 + rB * C2 + c) = make_float2(d[mi2][ni][2], d[mi2][ni][3]);
                }
            }
        }
    }
}

// ---------------- final layer ----------------
__global__ void k_final(const float* __restrict__ W3, const float* __restrict__ b3,
                        float* __restrict__ out)
{
    __shared__ float sw[64];
    int tid = threadIdx.x;
    if (tid < 64) sw[tid] = W3[tid];
    __syncthreads();
    int pos = blockIdx.x * 128 + (tid >> 1);
    int half = tid & 1;
    float acc = 0.f;
    if (pos < E_EDGES) {
        int g = g_gid[pos];
        const float4* xr = (const float4*)g_x2    + (size_t)pos * 16 + half * 8;
        const float4* mr = (const float4*)g_mean2 + g * 16 + half * 8;
        const float4* vr = (const float4*)g_inv2  + g * 16 + half * 8;
        #pragma unroll
        for (int j = 0; j < 8; j++) {
            float4 x = xr[j], m = mr[j], iv = vr[j];
            int k = half * 32 + j * 4;
            acc += fmaxf((x.x - m.x) * iv.x, 0.f) * sw[k]
                 + fmaxf((x.y - m.y) * iv.y, 0.f) * sw[k + 1]
                 + fmaxf((x.z - m.z) * iv.z, 0.f) * sw[k + 2]
                 + fmaxf((x.w - m.w) * iv.w, 0.f) * sw[k + 3];
        }
    }
    float other = __shfl_xor_sync(0xffffffffu, acc, 1);
    if (half == 0 && pos < E_EDGES) out[g_perm[pos]] = acc + other + b3[0];
}

// ---------------- launch ----------------
extern "C" void kernel_launch(void* const* d_in, const int* in_sizes, int n_in,
                              void* d_out, int out_size)
{
    const float* emb   = (const float*)d_in[0];
    const float* W1    = (const float*)d_in[1];
    const float* W2    = (const float*)d_in[3];
    const float* W3    = (const float*)d_in[5];
    const float* b3    = (const float*)d_in[6];
    const int*   ei    = (const int*)d_in[7];
    const int*   batch = (const int*)d_in[8];
    const int* col = ei;
    const int* row = ei + E_EDGES;
    float* out = (float*)d_out;

    static int attr_set = 0;
    if (!attr_set) {
        cudaFuncSetAttribute(k_gemm1_mma, cudaFuncAttributeMaxDynamicSharedMemorySize, 202752);
        cudaFuncSetAttribute(k_gemm2_mma, cudaFuncAttributeMaxDynamicSharedMemorySize, 202752);
        attr_set = 1;
    }

    k_zero<<<1, 512>>>();
    k_prep1<<<32, 512>>>(W1);
    k_prep2<<<16, 512>>>(W2);
    k_hist<<<1024, 256>>>(col, batch);
    k_scan<<<1, 512>>>();
    k_scatter<<<(E_EDGES + 2047) / 2048, 256>>>(col, batch);
    k_gemm1_mma<<<PGRID, 512, 202752>>>(emb, col, row);
    k_stats1<<<NG * 8, 256>>>();
    k_gemm2_mma<<<PGRID, 512, 202752>>>();
    k_stats2<<<NG * 2, 256>>>();
    k_final<<<EP / 128, 256>>>(W3, b3, out);
}

// round 5
// speedup vs baseline: 1.3719x; 1.2590x over previous
#include <cuda_runtime.h>
#include <cuda_bf16.h>
#include <cstdint>

// ExtractorMLP: per-edge MLP 128->256->64->1 with per-graph instance norm.
// R5: algebraic factorization — x1[e] = Y[col,0:256] + Y[row,256:512],
//     Y = emb @ [W1_top | W1_bot]  ([50000,512], 20x fewer GEMM1 FLOPs,
//     no 1GB x1 scratch). GEMM2 stays on mma.sync bf16 3-term split.

#define E_EDGES 1000000
#define EP      1000064   // multiple of 128
#define NG      512
#define NN      50000
#define C1      256
#define C2      64
#define EPS_IN  1e-5f
#define NTILES  (EP / 128)   // 7813
#define PGRID   148

typedef unsigned long long ull;
typedef unsigned int u32;

// ---------------- scratch ----------------
__device__ float g_Y[(size_t)NN * 512];   // 102 MB: [node][0:256]=emb@W1top, [256:512]=emb@W1bot
__device__ float g_x2[(size_t)EP * C2];
__device__ int   g_perm[EP];
__device__ int   g_gid[EP];
__device__ int   g_scol[EP];
__device__ int   g_srow[EP];
__device__ int   g_cnt[NG];
__device__ int   g_off[NG + 1];
__device__ int   g_cur[NG];
__device__ float g_mean1[NG * C1];
__device__ float g_inv1 [NG * C1];
__device__ float g_mean2[NG * C2];
__device__ float g_inv2 [NG * C2];
// W2 pre-split bf16 hi/lo in mma-fragment-direct order (dense, 64 u32/atom)
__device__ u32 g_B2hi[8192], g_B2lo[8192];   // 128 atoms (ni 8 x ki 16)

// ---------------- helpers ----------------
__device__ __forceinline__ ull pack2(float x, float y) {
    ull r; asm("mov.b64 %0, {%1, %2};" : "=l"(r) : "f"(x), "f"(y)); return r;
}
__device__ __forceinline__ void unpack2(ull v, float& x, float& y) {
    asm("mov.b64 {%0, %1}, %2;" : "=f"(x), "=f"(y) : "l"(v));
}
__device__ __forceinline__ void fma2(ull& d, ull a, ull b) {
    asm("fma.rn.f32x2 %0, %1, %2, %0;" : "+l"(d) : "l"(a), "l"(b));
}
__device__ __forceinline__ void bsplit(float x, float y, u32& h, u32& l) {
    __nv_bfloat162 hh = __floats2bfloat162_rn(x, y);
    float hx = __bfloat162float(hh.x);
    float hy = __bfloat162float(hh.y);
    __nv_bfloat162 ll = __floats2bfloat162_rn(x - hx, y - hy);
    h = *reinterpret_cast<u32*>(&hh);
    l = *reinterpret_cast<u32*>(&ll);
}
__device__ __forceinline__ void mma_bf16(float* d, const u32* a, const u32* b) {
    asm volatile(
        "mma.sync.aligned.m16n8k16.row.col.f32.bf16.bf16.f32 "
        "{%0,%1,%2,%3}, {%4,%5,%6,%7}, {%8,%9}, {%0,%1,%2,%3};"
        : "+f"(d[0]), "+f"(d[1]), "+f"(d[2]), "+f"(d[3])
        : "r"(a[0]), "r"(a[1]), "r"(a[2]), "r"(a[3]), "r"(b[0]), "r"(b[1]));
}
// A fragment scatter-store: element pair (bf16x2) at (m-local ml, k-pair kp)
__device__ __forceinline__ void a_store(u32* hiB, u32* loB, int atom_base_x_stride,
                                        int ml, int kpl, u32 h, u32 l) {
    int off = atom_base_x_stride + ((ml & 7) * 4 + (kpl & 3)) * 4
            + (ml >> 3) + 2 * (kpl >> 2);
    hiB[off] = h; loB[off] = l;
}

// ---------------- init ----------------
__global__ void k_zero() {
    int t = threadIdx.x;
    if (t < NG) g_cnt[t] = 0;
    if (t < (EP - E_EDGES)) {
        g_gid[E_EDGES + t] = 0;
        g_perm[E_EDGES + t] = 0;
        g_scol[E_EDGES + t] = 0;
        g_srow[E_EDGES + t] = 0;
    }
}

// W2 [256,64] -> mma B fragments, bf16 hi/lo
__global__ void k_prep2(const float* __restrict__ W2) {
    int idx = blockIdx.x * blockDim.x + threadIdx.x;
    if (idx >= 8192) return;
    int a = idx >> 6, l = (idx >> 1) & 31, r = idx & 1;
    int ng = a >> 4, ki = a & 15;
    int k = ki * 16 + (l & 3) * 2 + r * 8;
    int n = ng * 8 + (l >> 2);
    float v0 = W2[k * 64 + n], v1 = W2[(k + 1) * 64 + n];
    u32 h, lo; bsplit(v0, v1, h, lo);
    g_B2hi[idx] = h; g_B2lo[idx] = lo;
}

// ---------------- sort pipeline ----------------
__global__ void k_hist(const int* __restrict__ col, const int* __restrict__ batch) {
    __shared__ int h[NG];
    int t = threadIdx.x;
    for (int g = t; g < NG; g += blockDim.x) h[g] = 0;
    __syncthreads();
    int idx = blockIdx.x * blockDim.x + t;
    int stride = gridDim.x * blockDim.x;
    for (int e = idx; e < E_EDGES; e += stride)
        atomicAdd(&h[batch[col[e]]], 1);
    __syncthreads();
    for (int g = t; g < NG; g += blockDim.x)
        if (h[g]) atomicAdd(&g_cnt[g], h[g]);
}

__global__ void k_scan() {
    __shared__ int s[NG];
    int t = threadIdx.x;
    int c = g_cnt[t];
    s[t] = c;
    __syncthreads();
    for (int o = 1; o < NG; o <<= 1) {
        int v = (t >= o) ? s[t - o] : 0;
        __syncthreads();
        s[t] += v;
        __syncthreads();
    }
    int excl = s[t] - c;
    g_off[t] = excl;
    g_cur[t] = excl;
    if (t == NG - 1) g_off[NG] = s[t];
}

__global__ void k_scatter(const int* __restrict__ col, const int* __restrict__ row,
                          const int* __restrict__ batch) {
    __shared__ int sg[2048];
    __shared__ int hist[NG], base_[NG], cnt2[NG];
    int t = threadIdx.x;
    for (int g = t; g < NG; g += 256) { hist[g] = 0; cnt2[g] = 0; }
    __syncthreads();
    int e0 = blockIdx.x * 2048;
    #pragma unroll
    for (int j = 0; j < 8; j++) {
        int e = e0 + t + j * 256;
        int g = -1;
        if (e < E_EDGES) { g = batch[col[e]]; atomicAdd(&hist[g], 1); }
        sg[t + j * 256] = g;
    }
    __syncthreads();
    for (int g = t; g < NG; g += 256)
        if (hist[g]) base_[g] = atomicAdd(&g_cur[g], hist[g]);
    __syncthreads();
    #pragma unroll
    for (int j = 0; j < 8; j++) {
        int e = e0 + t + j * 256;
        if (e < E_EDGES) {
            int g = sg[t + j * 256];
            int l = atomicAdd(&cnt2[g], 1);
            int p = base_[g] + l;
            g_perm[p] = e;
            g_gid[p] = g;
            g_scol[p] = col[e];
            g_srow[p] = row[e];
        }
    }
}

// ---------------- Y = emb @ [W1top | W1bot]  ([50000,64] @ [64,512]) ----------------
// tile: 64 nodes x 128 cols, K=64, FFMA2 over node pairs.
__global__ __launch_bounds__(256) void k_emb(const float* __restrict__ emb,
                                             const float* __restrict__ W1)
{
    __shared__ float sE[64][66];    // [k][node]
    __shared__ float sW[64][128];   // [k][col]
    int nb = blockIdx.x * 64;
    int cb = blockIdx.y * 128;      // 0,128 -> W1 top half; 256,384 -> bottom half
    int tid = threadIdx.x;

    // load emb tile transposed
    for (int i = tid; i < 64 * 16; i += 256) {
        int node = i >> 4, f4 = i & 15;
        float4 v = make_float4(0.f, 0.f, 0.f, 0.f);
        if (nb + node < NN)
            v = ((const float4*)emb)[(size_t)(nb + node) * 16 + f4];
        int k = f4 * 4;
        sE[k    ][node] = v.x;
        sE[k + 1][node] = v.y;
        sE[k + 2][node] = v.z;
        sE[k + 3][node] = v.w;
    }
    // load W slice: rows k (or 64+k), cols cb..cb+127 within its half
    const float* Wsrc = (cb < 256) ? (W1 + cb) : (W1 + 64 * 256 + (cb - 256));
    for (int i = tid; i < 2048; i += 256) {
        int k = i >> 5, c4 = i & 31;
        ((float4*)sW[k])[c4] = ((const float4*)(Wsrc + (size_t)k * 256))[c4];
    }
    __syncthreads();

    int tn = tid >> 4, tc = tid & 15;   // 4 nodes (2 pairs), 8 cols
    ull acc[2][8];
    #pragma unroll
    for (int p = 0; p < 2; p++)
        #pragma unroll
        for (int j = 0; j < 8; j++) acc[p][j] = 0ull;

    #pragma unroll 8
    for (int k = 0; k < 64; k++) {
        ull p0 = *(const ull*)&sE[k][tn * 4];
        ull p1 = *(const ull*)&sE[k][tn * 4 + 2];
        float4 b0 = *(const float4*)&sW[k][tc * 8];
        float4 b1 = *(const float4*)&sW[k][tc * 8 + 4];
        float bs[8] = {b0.x, b0.y, b0.z, b0.w, b1.x, b1.y, b1.z, b1.w};
        #pragma unroll
        for (int j = 0; j < 8; j++) {
            ull bb = pack2(bs[j], bs[j]);
            fma2(acc[0][j], p0, bb);
            fma2(acc[1][j], p1, bb);
        }
    }
    #pragma unroll
    for (int p = 0; p < 2; p++) {
        float lo[8], hi[8];
        #pragma unroll
        for (int j = 0; j < 8; j++) unpack2(acc[p][j], lo[j], hi[j]);
        int n0 = nb + tn * 4 + 2 * p;
        if (n0 < NN) {
            float* r = g_Y + (size_t)n0 * 512 + cb + tc * 8;
            ((float4*)r)[0] = make_float4(lo[0], lo[1], lo[2], lo[3]);
            ((float4*)r)[1] = make_float4(lo[4], lo[5], lo[6], lo[7]);
        }
        if (n0 + 1 < NN) {
            float* r = g_Y + (size_t)(n0 + 1) * 512 + cb + tc * 8;
            ((float4*)r)[0] = make_float4(hi[0], hi[1], hi[2], hi[3]);
            ((float4*)r)[1] = make_float4(hi[4], hi[5], hi[6], hi[7]);
        }
    }
}

// ---------------- stats1: per (graph, 64-ch chunk), gather from Y ----------------
__global__ void k_stats1g() {
    int g  = blockIdx.x >> 2;
    int c0 = (blockIdx.x & 3) * 64;
    int t = threadIdx.x;
    int c = c0 + (t & 63), lane = t >> 6;
    int s = g_off[g], eend = g_off[g + 1];
    float S = 0.f, Q = 0.f;
    for (int p = s + lane; p < eend; p += 4) {
        int nc = g_scol[p], nr = g_srow[p];
        float v = g_Y[nc * 512 + c] + g_Y[nr * 512 + 256 + c];
        S += v; Q += v * v;
    }
    __shared__ float sS[256], sQ[256];
    sS[t] = S; sQ[t] = Q;
    __syncthreads();
    if (t < 128) { sS[t] += sS[t + 128]; sQ[t] += sQ[t + 128]; }
    __syncthreads();
    if (t < 64) {
        float Ssum = sS[t] + sS[t + 64];
        float Qsum = sQ[t] + sQ[t + 64];
        float cnt = (float)max(eend - s, 1);
        float m = Ssum / cnt;
        float var = Qsum / cnt - m * m;
        g_mean1[g * C1 + c0 + t] = m;
        g_inv1 [g * C1 + c0 + t] = rsqrtf(var + EPS_IN);
    }
}

// ---------------- GEMM2: mma.sync bf16 3-term; M=128,N=64,K=256 per tile ----------------
// A = relu(norm1(Y[col,0:256]+Y[row,256:512])) gathered per edge.
// smem (u32): [0) B2hi 128*66 | [8448) B2lo | [16896) A hi 128*132 | [33792) A lo
__global__ __launch_bounds__(512, 1) void k_gemm2_mma()
{
    extern __shared__ u32 sm[];
    u32* sBhi = sm;
    u32* sBlo = sm + 8448;
    u32* sAhi = sm + 16896;
    u32* sAlo = sm + 33792;

    int tid = threadIdx.x;
    for (int i = tid; i < 8192; i += 512) {
        int a = i >> 6, j = i & 63;
        sBhi[a * 66 + j] = g_B2hi[i];
        sBlo[a * 66 + j] = g_B2lo[i];
    }

    int w = tid >> 5, lane = tid & 31;
    int wm = w & 3, wn = w >> 2;        // M 32-slice, N 16-slice
    int m = tid >> 2, q = tid & 3;
    int mi = m >> 4, ml = m & 15;

    for (int tile = blockIdx.x; tile < NTILES; tile += PGRID) {
        int base = tile * 128;
        __syncthreads();
        // gather: Y[col]+Y[row] -> norm+relu -> split -> frag smem
        {
            int pos = base + m;
            int g = g_gid[pos];
            int nc = g_scol[pos], nr = g_srow[pos];
            const float4* yc = (const float4*)(g_Y + nc * 512) + q * 16;
            const float4* yr = (const float4*)(g_Y + nr * 512 + 256) + q * 16;
            const float4* mr = (const float4*)(g_mean1 + g * C1) + q * 16;
            const float4* vr = (const float4*)(g_inv1 + g * C1) + q * 16;
            #pragma unroll
            for (int jj = 0; jj < 16; jj++) {
                float4 a = yc[jj], b = yr[jj], mm = mr[jj], iv = vr[jj];
                float v0 = fmaxf((a.x + b.x - mm.x) * iv.x, 0.f);
                float v1 = fmaxf((a.y + b.y - mm.y) * iv.y, 0.f);
                float v2 = fmaxf((a.z + b.z - mm.z) * iv.z, 0.f);
                float v3 = fmaxf((a.w + b.w - mm.w) * iv.w, 0.f);
                u32 h0, l0, h1, l1;
                bsplit(v0, v1, h0, l0);
                bsplit(v2, v3, h1, l1);
                int kp0 = q * 32 + jj * 2;
                int ab0 = (mi * 16 + (kp0 >> 3)) * 132;
                a_store(sAhi, sAlo, ab0, ml, kp0 & 7, h0, l0);
                int kp1 = kp0 + 1;
                int ab1 = (mi * 16 + (kp1 >> 3)) * 132;
                a_store(sAhi, sAlo, ab1, ml, kp1 & 7, h1, l1);
            }
        }
        __syncthreads();
        float d[2][2][4];
        #pragma unroll
        for (int i2 = 0; i2 < 2; i2++)
            #pragma unroll
            for (int ni = 0; ni < 2; ni++)
                #pragma unroll
                for (int r = 0; r < 4; r++) d[i2][ni][r] = 0.f;

        #pragma unroll
        for (int ki = 0; ki < 16; ki++) {
            u32 ah[2][4], al[2][4];
            #pragma unroll
            for (int mi2 = 0; mi2 < 2; mi2++) {
                int atom = ((wm * 2 + mi2) * 16 + ki) * 132 + lane * 4;
                uint4 vh = *(const uint4*)(sAhi + atom);
                uint4 vl = *(const uint4*)(sAlo + atom);
                ah[mi2][0] = vh.x; ah[mi2][1] = vh.y; ah[mi2][2] = vh.z; ah[mi2][3] = vh.w;
                al[mi2][0] = vl.x; al[mi2][1] = vl.y; al[mi2][2] = vl.z; al[mi2][3] = vl.w;
            }
            #pragma unroll
            for (int ni = 0; ni < 2; ni++) {
                int batom = ((wn * 2 + ni) * 16 + ki) * 66 + lane * 2;
                uint2 bh = *(const uint2*)(sBhi + batom);
                uint2 bl = *(const uint2*)(sBlo + batom);
                u32 bhv[2] = {bh.x, bh.y};
                u32 blv[2] = {bl.x, bl.y};
                mma_bf16(d[0][ni], ah[0], bhv);
                mma_bf16(d[1][ni], ah[1], bhv);
                mma_bf16(d[0][ni], ah[0], blv);
                mma_bf16(d[1][ni], ah[1], blv);
                mma_bf16(d[0][ni], al[0], bhv);
                mma_bf16(d[1][ni], al[1], bhv);
            }
        }
        {
            int r0base = base + wm * 32 + (lane >> 2);
            int cbase = wn * 16 + (lane & 3) * 2;
            #pragma unroll
            for (int mi2 = 0; mi2 < 2; mi2++) {
                size_t rA = (size_t)(r0base + mi2 * 16);
                size_t rB = rA + 8;
                #pragma unroll
                for (int ni = 0; ni < 2; ni++) {
                    int c = cbase + ni * 8;
                    *(float2*)(g_x2 + rA * C2 + c) = make_float2(d[mi2][ni][0], d[mi2][ni][1]);
                    *(float2*)(g_x2 + rB * C2 + c) = make_float2(d[mi2][ni][2], d[mi2][ni][3]);
                }
            }
        }
    }
}

// ---------------- stats2 ----------------
__global__ void k_stats2() {
    int g  = blockIdx.x >> 1;
    int c0 = (blockIdx.x & 1) * 32;
    int t = threadIdx.x;
    int c = c0 + (t & 31), r = t >> 5;
    int s = g_off[g], eend = g_off[g + 1];
    float S = 0.f, Q = 0.f;
    for (int p = s + r; p < eend; p += 8) {
        float v = g_x2[(size_t)p * C2 + c];
        S += v; Q += v * v;
    }
    __shared__ float sS[256], sQ[256];
    sS[t] = S; sQ[t] = Q;
    __syncthreads();
    for (int h2 = 128; h2 >= 32; h2 >>= 1) {
        if (t < h2) { sS[t] += sS[t + h2]; sQ[t] += sQ[t + h2]; }
        __syncthreads();
    }
    if (t < 32) {
        float cnt = (float)max(eend - s, 1);
        float m = sS[t] / cnt;
        float var = sQ[t] / cnt - m * m;
        g_mean2[g * C2 + c0 + t] = m;
        g_inv2 [g * C2 + c0 + t] = rsqrtf(var + EPS_IN);
    }
}

// ---------------- final layer ----------------
__global__ void k_final(const float* __restrict__ W3, const float* __restrict__ b3,
                        float* __restrict__ out)
{
    __shared__ float sw[64];
    int tid = threadIdx.x;
    if (tid < 64) sw[tid] = W3[tid];
    __syncthreads();
    int pos = blockIdx.x * 128 + (tid >> 1);
    int half = tid & 1;
    float acc = 0.f;
    if (pos < E_EDGES) {
        int g = g_gid[pos];
        const float4* xr = (const float4*)g_x2    + (size_t)pos * 16 + half * 8;
        const float4* mr = (const float4*)g_mean2 + g * 16 + half * 8;
        const float4* vr = (const float4*)g_inv2  + g * 16 + half * 8;
        #pragma unroll
        for (int j = 0; j < 8; j++) {
            float4 x = xr[j], m = mr[j], iv = vr[j];
            int k = half * 32 + j * 4;
            acc += fmaxf((x.x - m.x) * iv.x, 0.f) * sw[k]
                 + fmaxf((x.y - m.y) * iv.y, 0.f) * sw[k + 1]
                 + fmaxf((x.z - m.z) * iv.z, 0.f) * sw[k + 2]
                 + fmaxf((x.w - m.w) * iv.w, 0.f) * sw[k + 3];
        }
    }
    float other = __shfl_xor_sync(0xffffffffu, acc, 1);
    if (half == 0 && pos < E_EDGES) out[g_perm[pos]] = acc + other + b3[0];
}

// ---------------- launch ----------------
extern "C" void kernel_launch(void* const* d_in, const int* in_sizes, int n_in,
                              void* d_out, int out_size)
{
    const float* emb   = (const float*)d_in[0];
    const float* W1    = (const float*)d_in[1];
    const float* W2    = (const float*)d_in[3];
    const float* W3    = (const float*)d_in[5];
    const float* b3    = (const float*)d_in[6];
    const int*   ei    = (const int*)d_in[7];
    const int*   batch = (const int*)d_in[8];
    const int* col = ei;
    const int* row = ei + E_EDGES;
    float* out = (float*)d_out;

    static int attr_set = 0;
    if (!attr_set) {
        cudaFuncSetAttribute(k_gemm2_mma, cudaFuncAttributeMaxDynamicSharedMemorySize, 202752);
        attr_set = 1;
    }

    k_zero<<<1, 512>>>();
    k_prep2<<<16, 512>>>(W2);
    k_hist<<<1024, 256>>>(col, batch);
    k_scan<<<1, 512>>>();
    k_scatter<<<(E_EDGES + 2047) / 2048, 256>>>(col, row, batch);
    k_emb<<<dim3((NN + 63) / 64, 4), 256>>>(emb, W1);
    k_stats1g<<<NG * 4, 256>>>();
    k_gemm2_mma<<<PGRID, 512, 202752>>>();
    k_stats2<<<NG * 2, 256>>>();
    k_final<<<EP / 128, 256>>>(W3, b3, out);
}

// round 7
// speedup vs baseline: 2.0845x; 1.5194x over previous
#include <cuda_runtime.h>
#include <cuda_bf16.h>
#include <cstdint>

// ExtractorMLP: per-edge MLP 128->256->64->1 with per-graph instance norm.
// R6: gemm2 A-side rebuilt: row-major swizzled bf16 hi/lo + ldmatrix.x4
//     (kills ~16-way STS bank conflicts of the fragment-direct layout);
//     producer lane remap for conflict-free STS.128; miv = mean*inv folding.

#define E_EDGES 1000000
#define EP      1000064   // multiple of 128
#define NG      512
#define NN      50000
#define C1      256
#define C2      64
#define EPS_IN  1e-5f
#define NTILES  (EP / 128)   // 7813
#define PGRID   148

typedef unsigned long long ull;
typedef unsigned int u32;

// ---------------- scratch ----------------
__device__ float g_Y[(size_t)NN * 512];
__device__ float g_x2[(size_t)EP * C2];
__device__ int   g_perm[EP];
__device__ int   g_gid[EP];
__device__ int   g_scol[EP];
__device__ int   g_srow[EP];
__device__ int   g_cnt[NG];
__device__ int   g_off[NG + 1];
__device__ int   g_cur[NG];
__device__ float g_mean1[NG * C1];
__device__ float g_inv1 [NG * C1];
__device__ float g_miv1 [NG * C1];
__device__ float g_mean2[NG * C2];
__device__ float g_inv2 [NG * C2];
__device__ float g_miv2 [NG * C2];
// W2 pre-split bf16 hi/lo in mma-fragment-direct order (dense, 64 u32/atom)
__device__ u32 g_B2hi[8192], g_B2lo[8192];   // 128 atoms (ni 8 x ki 16)

// ---------------- helpers ----------------
__device__ __forceinline__ ull pack2(float x, float y) {
    ull r; asm("mov.b64 %0, {%1, %2};" : "=l"(r) : "f"(x), "f"(y)); return r;
}
__device__ __forceinline__ void unpack2(ull v, float& x, float& y) {
    asm("mov.b64 {%0, %1}, %2;" : "=f"(x), "=f"(y) : "l"(v));
}
__device__ __forceinline__ void fma2(ull& d, ull a, ull b) {
    asm("fma.rn.f32x2 %0, %1, %2, %0;" : "+l"(d) : "l"(a), "l"(b));
}
__device__ __forceinline__ void bsplit(float x, float y, u32& h, u32& l) {
    __nv_bfloat162 hh = __floats2bfloat162_rn(x, y);
    float hx = __bfloat162float(hh.x);
    float hy = __bfloat162float(hh.y);
    __nv_bfloat162 ll = __floats2bfloat162_rn(x - hx, y - hy);
    h = *reinterpret_cast<u32*>(&hh);
    l = *reinterpret_cast<u32*>(&ll);
}
__device__ __forceinline__ void mma_bf16(float* d, const u32* a, const u32* b) {
    asm volatile(
        "mma.sync.aligned.m16n8k16.row.col.f32.bf16.bf16.f32 "
        "{%0,%1,%2,%3}, {%4,%5,%6,%7}, {%8,%9}, {%0,%1,%2,%3};"
        : "+f"(d[0]), "+f"(d[1]), "+f"(d[2]), "+f"(d[3])
        : "r"(a[0]), "r"(a[1]), "r"(a[2]), "r"(a[3]), "r"(b[0]), "r"(b[1]));
}
__device__ __forceinline__ void ldm_x4(u32* r, u32 addr) {
    asm volatile("ldmatrix.sync.aligned.m8n8.x4.shared.b16 {%0,%1,%2,%3}, [%4];"
        : "=r"(r[0]), "=r"(r[1]), "=r"(r[2]), "=r"(r[3]) : "r"(addr));
}
__device__ __forceinline__ u32 smem_u32(const void* p) {
    u32 a;
    asm("{ .reg .u64 t; cvta.to.shared.u64 t, %1; cvt.u32.u64 %0, t; }"
        : "=r"(a) : "l"(p));
    return a;
}

// ---------------- init ----------------
__global__ void k_zero() {
    int t = threadIdx.x;
    if (t < NG) g_cnt[t] = 0;
    if (t < (EP - E_EDGES)) {
        g_gid[E_EDGES + t] = 0;
        g_perm[E_EDGES + t] = 0;
        g_scol[E_EDGES + t] = 0;
        g_srow[E_EDGES + t] = 0;
    }
}

// W2 [256,64] -> mma B fragments, bf16 hi/lo
__global__ void k_prep2(const float* __restrict__ W2) {
    int idx = blockIdx.x * blockDim.x + threadIdx.x;
    if (idx >= 8192) return;
    int a = idx >> 6, l = (idx >> 1) & 31, r = idx & 1;
    int ng = a >> 4, ki = a & 15;
    int k = ki * 16 + (l & 3) * 2 + r * 8;
    int n = ng * 8 + (l >> 2);
    float v0 = W2[k * 64 + n], v1 = W2[(k + 1) * 64 + n];
    u32 h, lo; bsplit(v0, v1, h, lo);
    g_B2hi[idx] = h; g_B2lo[idx] = lo;
}

// ---------------- sort pipeline ----------------
__global__ void k_hist(const int* __restrict__ col, const int* __restrict__ batch) {
    __shared__ int h[NG];
    int t = threadIdx.x;
    for (int g = t; g < NG; g += blockDim.x) h[g] = 0;
    __syncthreads();
    int idx = blockIdx.x * blockDim.x + t;
    int stride = gridDim.x * blockDim.x;
    for (int e = idx; e < E_EDGES; e += stride)
        atomicAdd(&h[batch[col[e]]], 1);
    __syncthreads();
    for (int g = t; g < NG; g += blockDim.x)
        if (h[g]) atomicAdd(&g_cnt[g], h[g]);
}

__global__ void k_scan() {
    __shared__ int s[NG];
    int t = threadIdx.x;
    int c = g_cnt[t];
    s[t] = c;
    __syncthreads();
    for (int o = 1; o < NG; o <<= 1) {
        int v = (t >= o) ? s[t - o] : 0;
        __syncthreads();
        s[t] += v;
        __syncthreads();
    }
    int excl = s[t] - c;
    g_off[t] = excl;
    g_cur[t] = excl;
    if (t == NG - 1) g_off[NG] = s[t];
}

__global__ void k_scatter(const int* __restrict__ col, const int* __restrict__ row,
                          const int* __restrict__ batch) {
    __shared__ int sg[2048];
    __shared__ int hist[NG], base_[NG], cnt2[NG];
    int t = threadIdx.x;
    for (int g = t; g < NG; g += 256) { hist[g] = 0; cnt2[g] = 0; }
    __syncthreads();
    int e0 = blockIdx.x * 2048;
    #pragma unroll
    for (int j = 0; j < 8; j++) {
        int e = e0 + t + j * 256;
        int g = -1;
        if (e < E_EDGES) { g = batch[col[e]]; atomicAdd(&hist[g], 1); }
        sg[t + j * 256] = g;
    }
    __syncthreads();
    for (int g = t; g < NG; g += 256)
        if (hist[g]) base_[g] = atomicAdd(&g_cur[g], hist[g]);
    __syncthreads();
    #pragma unroll
    for (int j = 0; j < 8; j++) {
        int e = e0 + t + j * 256;
        if (e < E_EDGES) {
            int g = sg[t + j * 256];
            int l = atomicAdd(&cnt2[g], 1);
            int p = base_[g] + l;
            g_perm[p] = e;
            g_gid[p] = g;
            g_scol[p] = col[e];
            g_srow[p] = row[e];
        }
    }
}

// ---------------- Y = emb @ [W1top | W1bot] ----------------
__global__ __launch_bounds__(256) void k_emb(const float* __restrict__ emb,
                                             const float* __restrict__ W1)
{
    __shared__ float sE[64][66];
    __shared__ float sW[64][128];
    int nb = blockIdx.x * 64;
    int cb = blockIdx.y * 128;
    int tid = threadIdx.x;

    for (int i = tid; i < 64 * 16; i += 256) {
        int node = i >> 4, f4 = i & 15;
        float4 v = make_float4(0.f, 0.f, 0.f, 0.f);
        if (nb + node < NN)
            v = ((const float4*)emb)[(size_t)(nb + node) * 16 + f4];
        int k = f4 * 4;
        sE[k    ][node] = v.x;
        sE[k + 1][node] = v.y;
        sE[k + 2][node] = v.z;
        sE[k + 3][node] = v.w;
    }
    const float* Wsrc = (cb < 256) ? (W1 + cb) : (W1 + 64 * 256 + (cb - 256));
    for (int i = tid; i < 2048; i += 256) {
        int k = i >> 5, c4 = i & 31;
        ((float4*)sW[k])[c4] = ((const float4*)(Wsrc + (size_t)k * 256))[c4];
    }
    __syncthreads();

    int tn = tid >> 4, tc = tid & 15;
    ull acc[2][8];
    #pragma unroll
    for (int p = 0; p < 2; p++)
        #pragma unroll
        for (int j = 0; j < 8; j++) acc[p][j] = 0ull;

    #pragma unroll 8
    for (int k = 0; k < 64; k++) {
        ull p0 = *(const ull*)&sE[k][tn * 4];
        ull p1 = *(const ull*)&sE[k][tn * 4 + 2];
        float4 b0 = *(const float4*)&sW[k][tc * 8];
        float4 b1 = *(const float4*)&sW[k][tc * 8 + 4];
        float bs[8] = {b0.x, b0.y, b0.z, b0.w, b1.x, b1.y, b1.z, b1.w};
        #pragma unroll
        for (int j = 0; j < 8; j++) {
            ull bb = pack2(bs[j], bs[j]);
            fma2(acc[0][j], p0, bb);
            fma2(acc[1][j], p1, bb);
        }
    }
    #pragma unroll
    for (int p = 0; p < 2; p++) {
        float lo[8], hi[8];
        #pragma unroll
        for (int j = 0; j < 8; j++) unpack2(acc[p][j], lo[j], hi[j]);
        int n0 = nb + tn * 4 + 2 * p;
        if (n0 < NN) {
            float* r = g_Y + (size_t)n0 * 512 + cb + tc * 8;
            ((float4*)r)[0] = make_float4(lo[0], lo[1], lo[2], lo[3]);
            ((float4*)r)[1] = make_float4(lo[4], lo[5], lo[6], lo[7]);
        }
        if (n0 + 1 < NN) {
            float* r = g_Y + (size_t)(n0 + 1) * 512 + cb + tc * 8;
            ((float4*)r)[0] = make_float4(hi[0], hi[1], hi[2], hi[3]);
            ((float4*)r)[1] = make_float4(hi[4], hi[5], hi[6], hi[7]);
        }
    }
}

// ---------------- stats1: per (graph, 64-ch chunk), gather from Y ----------------
__global__ void k_stats1g() {
    int g  = blockIdx.x >> 2;
    int c0 = (blockIdx.x & 3) * 64;
    int t = threadIdx.x;
    int c = c0 + (t & 63), lane = t >> 6;
    int s = g_off[g], eend = g_off[g + 1];
    float S = 0.f, Q = 0.f;
    for (int p = s + lane; p < eend; p += 4) {
        int nc = g_scol[p], nr = g_srow[p];
        float v = g_Y[nc * 512 + c] + g_Y[nr * 512 + 256 + c];
        S += v; Q += v * v;
    }
    __shared__ float sS[256], sQ[256];
    sS[t] = S; sQ[t] = Q;
    __syncthreads();
    if (t < 128) { sS[t] += sS[t + 128]; sQ[t] += sQ[t + 128]; }
    __syncthreads();
    if (t < 64) {
        float Ssum = sS[t] + sS[t + 64];
        float Qsum = sQ[t] + sQ[t + 64];
        float cnt = (float)max(eend - s, 1);
        float m = Ssum / cnt;
        float var = Qsum / cnt - m * m;
        float iv = rsqrtf(var + EPS_IN);
        g_mean1[g * C1 + c0 + t] = m;
        g_inv1 [g * C1 + c0 + t] = iv;
        g_miv1 [g * C1 + c0 + t] = m * iv;
    }
}

// ---------------- GEMM2: mma.sync bf16 3-term, ldmatrix A path ----------------
// smem bytes: [0) B2hi 33792 | [33792) B2lo | [67584) A hi 64KB | [133120) A lo 64KB
// A layout: bf16 [128 edges][256 ch]; 16B granule index = m*32 + (octet ^ (m&7)).
__global__ __launch_bounds__(512, 1) void k_gemm2_mma()
{
    extern __shared__ u32 sm[];
    u32* sBhi = sm;
    u32* sBlo = sm + 8448;
    char* smc = (char*)sm;
    char* cAhi = smc + 67584;
    char* cAlo = smc + 133120;
    u32 aAhi = smem_u32(cAhi);
    u32 aAlo = smem_u32(cAlo);

    int tid = threadIdx.x;
    for (int i = tid; i < 8192; i += 512) {
        int a = i >> 6, j = i & 63;
        sBhi[a * 66 + j] = g_B2hi[i];
        sBlo[a * 66 + j] = g_B2lo[i];
    }

    int w = tid >> 5, lane = tid & 31;
    int wm = w & 3, wn = w >> 2;        // M 32-slice, N 16-slice
    // producer role: q = channel quarter (const per warp), m = edge 0..127
    int q = tid >> 7, m = tid & 127;
    int msw = m & 7;
    // consumer ldmatrix lane geometry
    int lt = lane >> 3, lr = lane & 7;
    int lrow8 = (lt & 1) * 8 + lr;      // row-in-atom (0..15)
    int lth = lt >> 1;                  // octet parity

    for (int tile = blockIdx.x; tile < NTILES; tile += PGRID) {
        int base = tile * 128;
        __syncthreads();   // A buffer free (prev mma done)
        // ---- gather: Y[col]+Y[row] -> norm+relu -> split -> swizzled rows ----
        {
            int pos = base + m;
            int g = g_gid[pos];
            int nc = g_scol[pos], nr = g_srow[pos];
            const float4* yc = (const float4*)(g_Y + nc * 512) + q * 16;
            const float4* yr = (const float4*)(g_Y + nr * 512 + 256) + q * 16;
            const float4* vr = (const float4*)(g_inv1 + g * C1) + q * 16;
            const float4* mv = (const float4*)(g_miv1 + g * C1) + q * 16;
            u32 hb0 = 0, hb1 = 0, lb0 = 0, lb1 = 0;
            #pragma unroll
            for (int jj = 0; jj < 16; jj++) {
                float4 a = yc[jj], b = yr[jj], iv = vr[jj], mm = mv[jj];
                float v0 = fmaxf(fmaf(a.x + b.x, iv.x, -mm.x), 0.f);
                float v1 = fmaxf(fmaf(a.y + b.y, iv.y, -mm.y), 0.f);
                float v2 = fmaxf(fmaf(a.z + b.z, iv.z, -mm.z), 0.f);
                float v3 = fmaxf(fmaf(a.w + b.w, iv.w, -mm.w), 0.f);
                u32 h0, l0, h1, l1;
                bsplit(v0, v1, h0, l0);
                bsplit(v2, v3, h1, l1);
                if ((jj & 1) == 0) { hb0 = h0; hb1 = h1; lb0 = l0; lb1 = l1; }
                else {
                    int ko = q * 8 + (jj >> 1);
                    int gran = m * 32 + (ko ^ msw);
                    *(uint4*)(cAhi + gran * 16) = make_uint4(hb0, hb1, h0, h1);
                    *(uint4*)(cAlo + gran * 16) = make_uint4(lb0, lb1, l0, l1);
                }
            }
        }
        __syncthreads();
        // ---- mma ----
        float d[2][2][4];
        #pragma unroll
        for (int i2 = 0; i2 < 2; i2++)
            #pragma unroll
            for (int ni = 0; ni < 2; ni++)
                #pragma unroll
                for (int r = 0; r < 4; r++) d[i2][ni][r] = 0.f;

        #pragma unroll
        for (int ki = 0; ki < 16; ki++) {
            u32 ah[2][4], al[2][4];
            #pragma unroll
            for (int mi2 = 0; mi2 < 2; mi2++) {
                int ml = (wm * 2 + mi2) * 16 + lrow8;
                int oct = 2 * ki + lth;
                u32 goff = (u32)(ml * 32 + (oct ^ (ml & 7))) * 16;
                ldm_x4(ah[mi2], aAhi + goff);
                ldm_x4(al[mi2], aAlo + goff);
            }
            #pragma unroll
            for (int ni = 0; ni < 2; ni++) {
                int batom = ((wn * 2 + ni) * 16 + ki) * 66 + lane * 2;
                uint2 bh = *(const uint2*)(sBhi + batom);
                uint2 bl = *(const uint2*)(sBlo + batom);
                u32 bhv[2] = {bh.x, bh.y};
                u32 blv[2] = {bl.x, bl.y};
                mma_bf16(d[0][ni], ah[0], bhv);
                mma_bf16(d[1][ni], ah[1], bhv);
                mma_bf16(d[0][ni], ah[0], blv);
                mma_bf16(d[1][ni], ah[1], blv);
                mma_bf16(d[0][ni], al[0], bhv);
                mma_bf16(d[1][ni], al[1], bhv);
            }
        }
        // ---- epilogue ----
        {
            int r0base = base + wm * 32 + (lane >> 2);
            int cbase = wn * 16 + (lane & 3) * 2;
            #pragma unroll
            for (int mi2 = 0; mi2 < 2; mi2++) {
                size_t rA = (size_t)(r0base + mi2 * 16);
                size_t rB = rA + 8;
                #pragma unroll
                for (int ni = 0; ni < 2; ni++) {
                    int c = cbase + ni * 8;
                    *(float2*)(g_x2 + rA * C2 + c) = make_float2(d[mi2][ni][0], d[mi2][ni][1]);
                    *(float2*)(g_x2 + rB * C2 + c) = make_float2(d[mi2][ni][2], d[mi2][ni][3]);
                }
            }
        }
    }
}

// ---------------- stats2 ----------------
__global__ void k_stats2() {
    int g  = blockIdx.x >> 1;
    int c0 = (blockIdx.x & 1) * 32;
    int t = threadIdx.x;
    int c = c0 + (t & 31), r = t >> 5;
    int s = g_off[g], eend = g_off[g + 1];
    float S = 0.f, Q = 0.f;
    for (int p = s + r; p < eend; p += 8) {
        float v = g_x2[(size_t)p * C2 + c];
        S += v; Q += v * v;
    }
    __shared__ float sS[256], sQ[256];
    sS[t] = S; sQ[t] = Q;
    __syncthreads();
    for (int h2 = 128; h2 >= 32; h2 >>= 1) {
        if (t < h2) { sS[t] += sS[t + h2]; sQ[t] += sQ[t + h2]; }
        __syncthreads();
    }
    if (t < 32) {
        float cnt = (float)max(eend - s, 1);
        float m = sS[t] / cnt;
        float var = sQ[t] / cnt - m * m;
        float iv = rsqrtf(var + EPS_IN);
        g_mean2[g * C2 + c0 + t] = m;
        g_inv2 [g * C2 + c0 + t] = iv;
        g_miv2 [g * C2 + c0 + t] = m * iv;
    }
}

// ---------------- final layer ----------------
__global__ void k_final(const float* __restrict__ W3, const float* __restrict__ b3,
                        float* __restrict__ out)
{
    __shared__ float sw[64];
    int tid = threadIdx.x;
    if (tid < 64) sw[tid] = W3[tid];
    __syncthreads();
    int pos = blockIdx.x * 128 + (tid >> 1);
    int half = tid & 1;
    float acc = 0.f;
    if (pos < E_EDGES) {
        int g = g_gid[pos];
        const float4* xr = (const float4*)g_x2    + (size_t)pos * 16 + half * 8;
        const float4* vr = (const float4*)g_inv2  + g * 16 + half * 8;
        const float4* mr = (const float4*)g_miv2  + g * 16 + half * 8;
        #pragma unroll
        for (int j = 0; j < 8; j++) {
            float4 x = xr[j], iv = vr[j], mv = mr[j];
            int k = half * 32 + j * 4;
            acc += fmaxf(fmaf(x.x, iv.x, -mv.x), 0.f) * sw[k]
                 + fmaxf(fmaf(x.y, iv.y, -mv.y), 0.f) * sw[k + 1]
                 + fmaxf(fmaf(x.z, iv.z, -mv.z), 0.f) * sw[k + 2]
                 + fmaxf(fmaf(x.w, iv.w, -mv.w), 0.f) * sw[k + 3];
        }
    }
    float other = __shfl_xor_sync(0xffffffffu, acc, 1);
    if (half == 0 && pos < E_EDGES) out[g_perm[pos]] = acc + other + b3[0];
}

// ---------------- launch ----------------
extern "C" void kernel_launch(void* const* d_in, const int* in_sizes, int n_in,
                              void* d_out, int out_size)
{
    const float* emb   = (const float*)d_in[0];
    const float* W1    = (const float*)d_in[1];
    const float* W2    = (const float*)d_in[3];
    const float* W3    = (const float*)d_in[5];
    const float* b3    = (const float*)d_in[6];
    const int*   ei    = (const int*)d_in[7];
    const int*   batch = (const int*)d_in[8];
    const int* col = ei;
    const int* row = ei + E_EDGES;
    float* out = (float*)d_out;

    static int attr_set = 0;
    if (!attr_set) {
        cudaFuncSetAttribute(k_gemm2_mma, cudaFuncAttributeMaxDynamicSharedMemorySize, 198656);
        attr_set = 1;
    }

    k_zero<<<1, 512>>>();
    k_prep2<<<16, 512>>>(W2);
    k_hist<<<1024, 256>>>(col, batch);
    k_scan<<<1, 512>>>();
    k_scatter<<<(E_EDGES + 2047) / 2048, 256>>>(col, row, batch);
    k_emb<<<dim3((NN + 63) / 64, 4), 256>>>(emb, W1);
    k_stats1g<<<NG * 4, 256>>>();
    k_gemm2_mma<<<PGRID, 512, 198656>>>();
    k_stats2<<<NG * 2, 256>>>();
    k_final<<<EP / 128, 256>>>(W3, b3, out);
}